// round 10
// baseline (speedup 1.0000x reference)
#include <cuda_runtime.h>
#include <stdint.h>
#include <math.h>

// NSF sine-source generator — SINGLE fused kernel.
// Inputs: f0 [32,800] f32, W [9,1] f32, b [1] f32, upp=240
// Output: concat( har [N], noise [N], uv [N] ) f32, N = 32*192000

#define SR_F 24000.0f
#define TWO_PI_F 6.2831853071795864769f

// ---------------------------------------------------------------------------
// threefry2x32 partitionable: element i -> counter (0,i), out = x0 ^ x1.
// ---------------------------------------------------------------------------
__device__ __forceinline__ uint32_t threefry_xor(uint32_t p1) {
    const uint32_t k0 = 0u, k1 = 1234u;
    const uint32_t k2 = k0 ^ k1 ^ 0x1BD11BDAu;
    uint32_t x0 = 0u + k0, x1 = p1 + k1;
#define TF_MIX(r) { x0 += x1; x1 = (x1 << (r)) | (x1 >> (32 - (r))); x1 ^= x0; }
    TF_MIX(13) TF_MIX(15) TF_MIX(26) TF_MIX(6)   x0 += k1; x1 += k2 + 1u;
    TF_MIX(17) TF_MIX(29) TF_MIX(16) TF_MIX(24)  x0 += k2; x1 += k0 + 2u;
    TF_MIX(13) TF_MIX(15) TF_MIX(26) TF_MIX(6)   x0 += k0; x1 += k1 + 3u;
    TF_MIX(17) TF_MIX(29) TF_MIX(16) TF_MIX(24)  x0 += k1; x1 += k2 + 4u;
    TF_MIX(13) TF_MIX(15) TF_MIX(26) TF_MIX(6)   x0 += k2; x1 += k0 + 5u;
#undef TF_MIX
    return x0 ^ x1;
}

// Giles erfinv, sqrt(2)*0.1/3 folded.
__device__ __forceinline__ float erfinv_scaled(float x) {
    float w = -__logf(fmaf(-x, x, 1.0f));
    float p;
    if (w < 5.0f) {
        w -= 2.5f;
        p =            2.81022636e-08f;
        p = fmaf(p, w, 3.43273939e-07f);
        p = fmaf(p, w, -3.5233877e-06f);
        p = fmaf(p, w, -4.39150654e-06f);
        p = fmaf(p, w, 0.00021858087f);
        p = fmaf(p, w, -0.00125372503f);
        p = fmaf(p, w, -0.00417768164f);
        p = fmaf(p, w, 0.246640727f);
        p = fmaf(p, w, 1.50140941f);
    } else {
        w = sqrtf(w) - 3.0f;
        p =            -0.000200214257f;
        p = fmaf(p, w, 0.000100950558f);
        p = fmaf(p, w, 0.00134934322f);
        p = fmaf(p, w, -0.00367342844f);
        p = fmaf(p, w, 0.00573950773f);
        p = fmaf(p, w, -0.0076224613f);
        p = fmaf(p, w, 0.00943887047f);
        p = fmaf(p, w, 1.00167406f);
        p = fmaf(p, w, 2.83297682f);
    }
    return p * x * 0.047140452079103168f;
}

__device__ __forceinline__ float bits_to_noise(uint32_t bits) {
    float v = __uint_as_float((bits >> 9) | 0x3f800000u);   // [1,2)
    const float lo = -0.99999994f;                           // nextafterf(-1,0)
    float u = fmaxf(lo, fmaf(v, 2.0f, -3.0f));
    return erfinv_scaled(u);
}

// Chebyshev harmonic sum + tanh from (sin, cos) of theta.
__device__ __forceinline__ float cheby_tanh(float s1, float c1,
                                            const float* w, float bb, float uvv) {
    const float c2 = 2.0f * c1;
    float sprev = 0.0f, scur = s1, acc = 0.0f;
    #pragma unroll
    for (int h = 0; h < 9; h++) {
        acc = fmaf(scur, w[h], acc);
        float snext = fmaf(c2, scur, -sprev);
        sprev = scur; scur = snext;
    }
    const float x = fmaf(uvv, acc, bb);
    const float eg = __expf(x + x);
    return 1.0f - __fdividef(2.0f, eg + 1.0f);
}

// ---------------------------------------------------------------------------
// Single fused kernel: block = 8 frames of one row. 240 threads, 8 samp/thr.
// Block-local prefix: smem row of c-values + double tree reduction.
// ---------------------------------------------------------------------------
__global__ void __launch_bounds__(240, 6)
fused_kernel(const float* __restrict__ f0,
             const float* __restrict__ W,
             const float* __restrict__ bias,
             float* __restrict__ out,
             int F, int N) {
    __shared__ float  cvals[800];
    __shared__ double red[256];

    const int f8 = blockIdx.x;                 // 0..F/8-1
    const int b  = blockIdx.y;
    const int t  = threadIdx.x;                // 0..239
    const int start = f8 * 8;

    // ---- load whole row of c = f32(f0/24000) into smem ----
    const float* row = f0 + b * F;
    for (int j = t; j < 800; j += 240)
        cvals[j] = row[j] / SR_F;              // IEEE f32 division rounding
    if (t < 16) red[240 + t] = 0.0;
    __syncthreads();

    // ---- P0 = sum_{j < start} cvals[j], double tree reduction ----
    double ps = 0.0;
    for (int j = t; j < start; j += 240) ps += (double)cvals[j];
    red[t] = ps;
    __syncthreads();
    #pragma unroll
    for (int sstep = 128; sstep >= 1; sstep >>= 1) {
        if (t < sstep) red[t] += red[t + sstep];
        __syncthreads();
    }
    const double P0 = red[0];

    // ---- this thread's frame and sample range ----
    const int fi = t / 30;                     // frame within block (0..7)
    const int i0 = (t - fi * 30) * 8;          // sample within frame
    const int fr = b * F + start + fi;

    double Pf = P0;
    #pragma unroll
    for (int k = 0; k < 7; k++)
        if (k < fi) Pf += (double)cvals[start + k];

    const double p  = Pf * 240.0;
    const double fd = p - floor(p);            // frac, exact in double
    const float  hi = (float)fd;
    const float  lo = (float)(fd - (double)hi);

    const float c   = cvals[start + fi];
    const float uvv = (c > 0.0f) ? 1.0f : 0.0f;   // f0>0 <=> c>0
    const float bb  = __ldg(bias);

    float w[9];
    #pragma unroll
    for (int h = 0; h < 9; h++) w[h] = 0.1f * __ldg(&W[h]);

    const uint32_t idx = (uint32_t)fr * 240u + (uint32_t)i0;
    float* __restrict__ harp = out + idx;
    float* __restrict__ noip = out + N + idx;
    float* __restrict__ uvp  = out + 2 * N + idx;

    // ---- 8 independent hash chains ----
    uint32_t hbits[8];
    #pragma unroll
    for (int j = 0; j < 8; j++)
        hbits[j] = threefry_xor(idx + (uint32_t)j);

    float4 nq0, nq1;
    nq0.x = bits_to_noise(hbits[0]);
    nq0.y = bits_to_noise(hbits[1]);
    nq0.z = bits_to_noise(hbits[2]);
    nq0.w = bits_to_noise(hbits[3]);
    nq1.x = bits_to_noise(hbits[4]);
    nq1.y = bits_to_noise(hbits[5]);
    nq1.z = bits_to_noise(hbits[6]);
    nq1.w = bits_to_noise(hbits[7]);
    *(float4*)noip       = nq0;
    *(float4*)(noip + 4) = nq1;

    // ---- har via one sincos + rotation by delta = 2*pi*c per sample ----
    {
        float m = hi + (lo + c * (float)(i0 + 1));
        m -= (m >= 0.5f) ? 1.0f : 0.0f;
        const float th = m * TWO_PI_F;
        float s  = __sinf(th);
        float co = __cosf(th);
        const float dm = c * TWO_PI_F;
        const float sc = __sinf(dm);
        const float cc = __cosf(dm);

        float4 hq;
        #pragma unroll
        for (int q = 0; q < 2; q++) {
            #pragma unroll
            for (int k = 0; k < 4; k++) {
                (&hq.x)[k] = cheby_tanh(s, co, w, bb, uvv);
                float sn = fmaf(s, cc, co * sc);
                float cn = fmaf(co, cc, -(s * sc));
                s = sn; co = cn;
            }
            *(float4*)(harp + 4 * q) = hq;
        }
    }

    const float4 uq = make_float4(uvv, uvv, uvv, uvv);
    *(float4*)uvp       = uq;
    *(float4*)(uvp + 4) = uq;
}

// ---------------------------------------------------------------------------
extern "C" void kernel_launch(void* const* d_in, const int* in_sizes, int n_in,
                              void* d_out, int out_size) {
    const float* f0   = (const float*)d_in[0];
    const float* W    = (const float*)d_in[1];
    const float* bias = (const float*)d_in[2];
    float* out = (float*)d_out;

    const int F = 800;
    const int B = in_sizes[0] / F;      // 32
    const int N = out_size / 3;         // 6,144,000

    dim3 grid(F / 8, B);
    fused_kernel<<<grid, 240>>>(f0, W, bias, out, F, N);
}

// round 12
// speedup vs baseline: 1.2535x; 1.2535x over previous
#include <cuda_runtime.h>
#include <stdint.h>
#include <math.h>

// NSF sine-source generator — single fused kernel w/ cheap FP32 smem prefix.
// Inputs: f0 [32,800] f32, W [9,1] f32, b [1] f32, upp=240
// Output: concat( har [N], noise [N], uv [N] ) f32, N = 32*192000

#define SR_F 24000.0f
#define TWO_PI_F 6.2831853071795864769f

// ---------------------------------------------------------------------------
// threefry2x32 partitionable: element i -> counter (0,i), out = x0 ^ x1.
// ---------------------------------------------------------------------------
__device__ __forceinline__ uint32_t threefry_xor(uint32_t p1) {
    const uint32_t k0 = 0u, k1 = 1234u;
    const uint32_t k2 = k0 ^ k1 ^ 0x1BD11BDAu;
    uint32_t x0 = 0u + k0, x1 = p1 + k1;
#define TF_MIX(r) { x0 += x1; x1 = (x1 << (r)) | (x1 >> (32 - (r))); x1 ^= x0; }
    TF_MIX(13) TF_MIX(15) TF_MIX(26) TF_MIX(6)   x0 += k1; x1 += k2 + 1u;
    TF_MIX(17) TF_MIX(29) TF_MIX(16) TF_MIX(24)  x0 += k2; x1 += k0 + 2u;
    TF_MIX(13) TF_MIX(15) TF_MIX(26) TF_MIX(6)   x0 += k0; x1 += k1 + 3u;
    TF_MIX(17) TF_MIX(29) TF_MIX(16) TF_MIX(24)  x0 += k1; x1 += k2 + 4u;
    TF_MIX(13) TF_MIX(15) TF_MIX(26) TF_MIX(6)   x0 += k2; x1 += k0 + 5u;
#undef TF_MIX
    return x0 ^ x1;
}

// Giles erfinv, sqrt(2)*0.1/3 folded.
__device__ __forceinline__ float erfinv_scaled(float x) {
    float w = -__logf(fmaf(-x, x, 1.0f));
    float p;
    if (w < 5.0f) {
        w -= 2.5f;
        p =            2.81022636e-08f;
        p = fmaf(p, w, 3.43273939e-07f);
        p = fmaf(p, w, -3.5233877e-06f);
        p = fmaf(p, w, -4.39150654e-06f);
        p = fmaf(p, w, 0.00021858087f);
        p = fmaf(p, w, -0.00125372503f);
        p = fmaf(p, w, -0.00417768164f);
        p = fmaf(p, w, 0.246640727f);
        p = fmaf(p, w, 1.50140941f);
    } else {
        w = sqrtf(w) - 3.0f;
        p =            -0.000200214257f;
        p = fmaf(p, w, 0.000100950558f);
        p = fmaf(p, w, 0.00134934322f);
        p = fmaf(p, w, -0.00367342844f);
        p = fmaf(p, w, 0.00573950773f);
        p = fmaf(p, w, -0.0076224613f);
        p = fmaf(p, w, 0.00943887047f);
        p = fmaf(p, w, 1.00167406f);
        p = fmaf(p, w, 2.83297682f);
    }
    return p * x * 0.047140452079103168f;
}

__device__ __forceinline__ float bits_to_noise(uint32_t bits) {
    float v = __uint_as_float((bits >> 9) | 0x3f800000u);   // [1,2)
    const float lo = -0.99999994f;                           // nextafterf(-1,0)
    float u = fmaxf(lo, fmaf(v, 2.0f, -3.0f));
    return erfinv_scaled(u);
}

// Chebyshev harmonic sum + tanh from (sin, cos) of theta.
__device__ __forceinline__ float cheby_tanh(float s1, float c1,
                                            const float* w, float bb, float uvv) {
    const float c2 = 2.0f * c1;
    float sprev = 0.0f, scur = s1, acc = 0.0f;
    #pragma unroll
    for (int h = 0; h < 9; h++) {
        acc = fmaf(scur, w[h], acc);
        float snext = fmaf(c2, scur, -sprev);
        sprev = scur; scur = snext;
    }
    const float x = fmaf(uvv, acc, bb);
    const float eg = __expf(x + x);
    return 1.0f - __fdividef(2.0f, eg + 1.0f);
}

// 2sum accumulate: (s,e) += c exactly.
#define TWOSUM(s, e, cadd) { float _t = (s) + (cadd); float _z = _t - (s); \
    (e) += ((s) - (_t - _z)) + ((cadd) - _z); (s) = _t; }

// ---------------------------------------------------------------------------
// Single fused kernel: block = 8 frames of one row, 240 threads, 8 samp/thr.
// Preamble (FP32 only, 3 barriers): row->smem, warp-0 chunk scan, 8-thread
// frame prefixes. Body identical to the validated round-8 kernel.
// ---------------------------------------------------------------------------
__global__ void __launch_bounds__(240, 7)
fused_kernel(const float* __restrict__ f0,
             const float* __restrict__ W,
             const float* __restrict__ bias,
             float* __restrict__ out,
             int F, int N) {
    __shared__ float  cvals[800];
    __shared__ float2 chunkpref[32];   // exclusive prefix at multiples of 25
    __shared__ float2 pf8[8];          // frac(prefix*240) hi/lo per frame

    const int f8 = blockIdx.x;         // 0..99
    const int b  = blockIdx.y;
    const int t  = threadIdx.x;        // 0..239
    const int start = f8 * 8;

    // ---- stage 1: row of c = f32(f0/24000) into smem ----
    const float* row = f0 + b * F;
    #pragma unroll
    for (int j = t; j < 800; j += 240)
        cvals[j] = row[j] / SR_F;      // IEEE f32 division rounding
    __syncthreads();

    // ---- stage 2: warp 0 computes 32 chunk-exclusive prefixes (2sum) ----
    if (t < 32) {
        float s = 0.0f, e = 0.0f;
        #pragma unroll
        for (int j = 0; j < 25; j++) {
            float c = cvals[t * 25 + j];
            TWOSUM(s, e, c)
        }
        #pragma unroll
        for (int off = 1; off < 32; off <<= 1) {
            float so = __shfl_up_sync(0xffffffffu, s, off);
            float eo = __shfl_up_sync(0xffffffffu, e, off);
            if (t >= off) { e += eo; TWOSUM(s, e, so) }
        }
        float sx = __shfl_up_sync(0xffffffffu, s, 1);
        float ex = __shfl_up_sync(0xffffffffu, e, 1);
        if (t == 0) { sx = 0.0f; ex = 0.0f; }
        chunkpref[t] = make_float2(sx, ex);
    }
    __syncthreads();

    // ---- stage 3: threads 0..7 -> frame prefixes for this block ----
    if (t < 8) {
        const int pos = start + t;         // global frame index in row
        const int q = pos / 25;
        const int r = pos - q * 25;
        float2 cp = chunkpref[q];
        float s = cp.x, e = cp.y;
        for (int j = 0; j < r; j++) {
            float c = cvals[q * 25 + j];
            TWOSUM(s, e, c)
        }
        float ph = s * 240.0f;
        float pl = fmaf(s, 240.0f, -ph) + e * 240.0f;
        float fl = floorf(ph + pl);
        pf8[t] = make_float2(ph - fl, pl);
    }
    __syncthreads();

    // ---- body (validated round-8 structure) ----
    const int fi = t / 30;
    const int i0 = (t - fi * 30) * 8;
    const int fr = b * F + start + fi;

    const float2 pf = pf8[fi];
    const float c   = cvals[start + fi];
    const float uvv = (c > 0.0f) ? 1.0f : 0.0f;
    const float bb  = __ldg(bias);

    float w[9];
    #pragma unroll
    for (int h = 0; h < 9; h++) w[h] = 0.1f * __ldg(&W[h]);

    const uint32_t idx = (uint32_t)fr * 240u + (uint32_t)i0;
    float* __restrict__ harp = out + idx;
    float* __restrict__ noip = out + N + idx;
    float* __restrict__ uvp  = out + 2 * N + idx;

    // 8 independent hash chains
    uint32_t hbits[8];
    #pragma unroll
    for (int j = 0; j < 8; j++)
        hbits[j] = threefry_xor(idx + (uint32_t)j);

    float4 nq0, nq1;
    nq0.x = bits_to_noise(hbits[0]);
    nq0.y = bits_to_noise(hbits[1]);
    nq0.z = bits_to_noise(hbits[2]);
    nq0.w = bits_to_noise(hbits[3]);
    nq1.x = bits_to_noise(hbits[4]);
    nq1.y = bits_to_noise(hbits[5]);
    nq1.z = bits_to_noise(hbits[6]);
    nq1.w = bits_to_noise(hbits[7]);
    *(float4*)noip       = nq0;
    *(float4*)(noip + 4) = nq1;

    // har via one sincos + rotation by delta = 2*pi*c per sample
    {
        float m = pf.x + (pf.y + c * (float)(i0 + 1));
        m -= (m >= 0.5f) ? 1.0f : 0.0f;
        const float th = m * TWO_PI_F;
        float s  = __sinf(th);
        float co = __cosf(th);
        const float dm = c * TWO_PI_F;
        const float sc = __sinf(dm);
        const float cc = __cosf(dm);

        float4 hq;
        #pragma unroll
        for (int q = 0; q < 2; q++) {
            #pragma unroll
            for (int k = 0; k < 4; k++) {
                (&hq.x)[k] = cheby_tanh(s, co, w, bb, uvv);
                float sn = fmaf(s, cc, co * sc);
                float cn = fmaf(co, cc, -(s * sc));
                s = sn; co = cn;
            }
            *(float4*)(harp + 4 * q) = hq;
        }
    }

    const float4 uq = make_float4(uvv, uvv, uvv, uvv);
    *(float4*)uvp       = uq;
    *(float4*)(uvp + 4) = uq;
}

// ---------------------------------------------------------------------------
extern "C" void kernel_launch(void* const* d_in, const int* in_sizes, int n_in,
                              void* d_out, int out_size) {
    const float* f0   = (const float*)d_in[0];
    const float* W    = (const float*)d_in[1];
    const float* bias = (const float*)d_in[2];
    float* out = (float*)d_out;

    const int F = 800;
    const int B = in_sizes[0] / F;      // 32
    const int N = out_size / 3;         // 6,144,000

    dim3 grid(F / 8, B);
    fused_kernel<<<grid, 240>>>(f0, W, bias, out, F, N);
}

// round 13
// speedup vs baseline: 1.3679x; 1.0912x over previous
#include <cuda_runtime.h>
#include <stdint.h>
#include <math.h>

// NSF sine-source generator — prefix kernel + PDL-overlapped fused kernel.
// Inputs: f0 [32,800] f32, W [9,1] f32, b [1] f32, upp=240
// Output: concat( har [N], noise [N], uv [N] ) f32, N = 32*192000

#define SR_F 24000.0f
#define TWO_PI_F 6.2831853071795864769f

// frac(prefix * upp) per frame as float-float (hi, lo).
__device__ float2 g_prefix2[32 * 800];

// 2sum accumulate: (s,e) += c exactly.
#define TWOSUM(s, e, cadd) { float _t = (s) + (cadd); float _z = _t - (s); \
    (e) += ((s) - (_t - _z)) + ((cadd) - _z); (s) = _t; }

// ---------------------------------------------------------------------------
// Kernel A: one warp per row, FP32 compensated (2sum) arithmetic. (validated)
// ---------------------------------------------------------------------------
__global__ void frame_prefix_kernel(const float* __restrict__ f0, int F) {
    const int b = blockIdx.x;
    const int lane = threadIdx.x;
    const float* row = f0 + b * F;

    float cf[25];
    #pragma unroll
    for (int j = 0; j < 25; j++)
        cf[j] = row[lane * 25 + j] / SR_F;

    float s = 0.0f, e = 0.0f;
    #pragma unroll
    for (int j = 0; j < 25; j++) { TWOSUM(s, e, cf[j]) }

    #pragma unroll
    for (int off = 1; off < 32; off <<= 1) {
        float so = __shfl_up_sync(0xffffffffu, s, off);
        float eo = __shfl_up_sync(0xffffffffu, e, off);
        if (lane >= off) { e += eo; TWOSUM(s, e, so) }
    }
    float sx = __shfl_up_sync(0xffffffffu, s, 1);
    float ex = __shfl_up_sync(0xffffffffu, e, 1);
    if (lane == 0) { sx = 0.0f; ex = 0.0f; }

    const int base = b * F + lane * 25;
    #pragma unroll
    for (int j = 0; j < 25; j++) {
        float ph = sx * 240.0f;
        float pl = fmaf(sx, 240.0f, -ph) + ex * 240.0f;
        float fl = floorf(ph + pl);
        g_prefix2[base + j] = make_float2(ph - fl, pl);
        TWOSUM(sx, ex, cf[j])
    }
}

// ---------------------------------------------------------------------------
// threefry2x32 partitionable: element i -> counter (0,i), out = x0 ^ x1.
// ---------------------------------------------------------------------------
__device__ __forceinline__ uint32_t threefry_xor(uint32_t p1) {
    const uint32_t k0 = 0u, k1 = 1234u;
    const uint32_t k2 = k0 ^ k1 ^ 0x1BD11BDAu;
    uint32_t x0 = 0u + k0, x1 = p1 + k1;
#define TF_MIX(r) { x0 += x1; x1 = (x1 << (r)) | (x1 >> (32 - (r))); x1 ^= x0; }
    TF_MIX(13) TF_MIX(15) TF_MIX(26) TF_MIX(6)   x0 += k1; x1 += k2 + 1u;
    TF_MIX(17) TF_MIX(29) TF_MIX(16) TF_MIX(24)  x0 += k2; x1 += k0 + 2u;
    TF_MIX(13) TF_MIX(15) TF_MIX(26) TF_MIX(6)   x0 += k0; x1 += k1 + 3u;
    TF_MIX(17) TF_MIX(29) TF_MIX(16) TF_MIX(24)  x0 += k1; x1 += k2 + 4u;
    TF_MIX(13) TF_MIX(15) TF_MIX(26) TF_MIX(6)   x0 += k2; x1 += k0 + 5u;
#undef TF_MIX
    return x0 ^ x1;
}

// Giles erfinv, sqrt(2)*0.1/3 folded.
__device__ __forceinline__ float erfinv_scaled(float x) {
    float w = -__logf(fmaf(-x, x, 1.0f));
    float p;
    if (w < 5.0f) {
        w -= 2.5f;
        p =            2.81022636e-08f;
        p = fmaf(p, w, 3.43273939e-07f);
        p = fmaf(p, w, -3.5233877e-06f);
        p = fmaf(p, w, -4.39150654e-06f);
        p = fmaf(p, w, 0.00021858087f);
        p = fmaf(p, w, -0.00125372503f);
        p = fmaf(p, w, -0.00417768164f);
        p = fmaf(p, w, 0.246640727f);
        p = fmaf(p, w, 1.50140941f);
    } else {
        w = sqrtf(w) - 3.0f;
        p =            -0.000200214257f;
        p = fmaf(p, w, 0.000100950558f);
        p = fmaf(p, w, 0.00134934322f);
        p = fmaf(p, w, -0.00367342844f);
        p = fmaf(p, w, 0.00573950773f);
        p = fmaf(p, w, -0.0076224613f);
        p = fmaf(p, w, 0.00943887047f);
        p = fmaf(p, w, 1.00167406f);
        p = fmaf(p, w, 2.83297682f);
    }
    return p * x * 0.047140452079103168f;
}

__device__ __forceinline__ float bits_to_noise(uint32_t bits) {
    float v = __uint_as_float((bits >> 9) | 0x3f800000u);   // [1,2)
    const float lo = -0.99999994f;                           // nextafterf(-1,0)
    float u = fmaxf(lo, fmaf(v, 2.0f, -3.0f));
    return erfinv_scaled(u);
}

// Chebyshev harmonic sum + tanh from (sin, cos) of theta.
__device__ __forceinline__ float cheby_tanh(float s1, float c1,
                                            const float* w, float bb, float uvv) {
    const float c2 = 2.0f * c1;
    float sprev = 0.0f, scur = s1, acc = 0.0f;
    #pragma unroll
    for (int h = 0; h < 9; h++) {
        acc = fmaf(scur, w[h], acc);
        float snext = fmaf(c2, scur, -sprev);
        sprev = scur; scur = snext;
    }
    const float x = fmaf(uvv, acc, bb);
    const float eg = __expf(x + x);
    return 1.0f - __fdividef(2.0f, eg + 1.0f);
}

// ---------------------------------------------------------------------------
// Fused kernel (PDL secondary): noise+uv first (independent of prefix),
// then cudaGridDependencySynchronize(), then har from g_prefix2.
// Grid (F/8, B), 240 threads, 8 samples/thread.
// ---------------------------------------------------------------------------
__global__ void __launch_bounds__(240, 7)
fused_kernel(const float* __restrict__ f0,
             const float* __restrict__ W,
             const float* __restrict__ bias,
             float* __restrict__ out,
             int F, int N) {
    const int f8 = blockIdx.x;                 // 0..F/8-1
    const int b  = blockIdx.y;
    const int t  = threadIdx.x;                // 0..239
    const int fi = t / 30;
    const int i0 = (t - fi * 30) * 8;
    const int fr = b * F + f8 * 8 + fi;

    const uint32_t idx = (uint32_t)fr * 240u + (uint32_t)i0;
    float* __restrict__ harp = out + idx;
    float* __restrict__ noip = out + N + idx;
    float* __restrict__ uvp  = out + 2 * N + idx;

    // ---- phase 1 (prefix-independent): noise + uv ----
    uint32_t hbits[8];
    #pragma unroll
    for (int j = 0; j < 8; j++)
        hbits[j] = threefry_xor(idx + (uint32_t)j);

    float4 nq0, nq1;
    nq0.x = bits_to_noise(hbits[0]);
    nq0.y = bits_to_noise(hbits[1]);
    nq0.z = bits_to_noise(hbits[2]);
    nq0.w = bits_to_noise(hbits[3]);
    nq1.x = bits_to_noise(hbits[4]);
    nq1.y = bits_to_noise(hbits[5]);
    nq1.z = bits_to_noise(hbits[6]);
    nq1.w = bits_to_noise(hbits[7]);
    *(float4*)noip       = nq0;
    *(float4*)(noip + 4) = nq1;

    const float f0v = __ldg(&f0[fr]);
    const float uvv = (f0v > 0.0f) ? 1.0f : 0.0f;
    const float4 uq = make_float4(uvv, uvv, uvv, uvv);
    *(float4*)uvp       = uq;
    *(float4*)(uvp + 4) = uq;

    const float c  = __fdividef(f0v, SR_F);
    const float bb = __ldg(bias);
    float w[9];
    #pragma unroll
    for (int h = 0; h < 9; h++) w[h] = 0.1f * __ldg(&W[h]);

    // ---- wait for prefix kernel's g_prefix2 writes ----
    cudaGridDependencySynchronize();

    const float2 pf = g_prefix2[fr];

    // ---- phase 2: har via one sincos + rotation by delta = 2*pi*c ----
    {
        float m = pf.x + (pf.y + c * (float)(i0 + 1));
        m -= (m >= 0.5f) ? 1.0f : 0.0f;
        const float th = m * TWO_PI_F;
        float s  = __sinf(th);
        float co = __cosf(th);
        const float dm = c * TWO_PI_F;
        const float sc = __sinf(dm);
        const float cc = __cosf(dm);

        float4 hq;
        #pragma unroll
        for (int q = 0; q < 2; q++) {
            #pragma unroll
            for (int k = 0; k < 4; k++) {
                (&hq.x)[k] = cheby_tanh(s, co, w, bb, uvv);
                float sn = fmaf(s, cc, co * sc);
                float cn = fmaf(co, cc, -(s * sc));
                s = sn; co = cn;
            }
            *(float4*)(harp + 4 * q) = hq;
        }
    }
}

// ---------------------------------------------------------------------------
extern "C" void kernel_launch(void* const* d_in, const int* in_sizes, int n_in,
                              void* d_out, int out_size) {
    const float* f0   = (const float*)d_in[0];
    const float* W    = (const float*)d_in[1];
    const float* bias = (const float*)d_in[2];
    float* out = (float*)d_out;

    const int F = 800;
    const int B = in_sizes[0] / F;      // 32
    const int N = out_size / 3;         // 6,144,000

    frame_prefix_kernel<<<B, 32>>>(f0, F);

    // Secondary launch with programmatic stream serialization (PDL):
    // may begin while frame_prefix_kernel is still running; the device-side
    // cudaGridDependencySynchronize() enforces the data dependency.
    cudaLaunchConfig_t cfg = {};
    cfg.gridDim  = dim3(F / 8, B, 1);
    cfg.blockDim = dim3(240, 1, 1);
    cfg.dynamicSmemBytes = 0;
    cfg.stream = 0;
    cudaLaunchAttribute attrs[1];
    attrs[0].id = cudaLaunchAttributeProgrammaticStreamSerialization;
    attrs[0].val.programmaticStreamSerializationAllowed = 1;
    cfg.attrs = attrs;
    cfg.numAttrs = 1;

    cudaError_t err = cudaLaunchKernelEx(&cfg, fused_kernel,
                                         f0, W, bias, out, F, N);
    if (err != cudaSuccess) {
        // Fallback: plain dependent launch (still correct, just serialized).
        dim3 grid(F / 8, B);
        fused_kernel<<<grid, 240>>>(f0, W, bias, out, F, N);
    }
}